// round 5
// baseline (speedup 1.0000x reference)
#include <cuda_runtime.h>

#define NBLK 128
#define NTHR 256
#define B 256
#define TE 300
#define TT 600
#define H 512
#define NIN 128
#define NPV 5
#define EMBD 32
#define NHE 16

typedef unsigned long long ull;

__device__ float g_h0a[B * H], g_h0b[B * H];
__device__ float g_h1a[B * H], g_h1b[B * H];
__device__ float g_z[B * 256];
__device__ float g_pv[B * NPV];
__device__ float g_embs[B * EMBD];
__device__ unsigned g_bar_count;
__device__ unsigned g_bar_sense;

__device__ __forceinline__ void gsync(unsigned& sense) {
    __syncthreads();
    if (threadIdx.x == 0) {
        __threadfence();
        unsigned prev = atomicAdd(&g_bar_count, 1u);
        if (prev == (unsigned)(NBLK - 1)) {
            atomicExch(&g_bar_count, 0u);
            __threadfence();
            *((volatile unsigned*)&g_bar_sense) = sense ^ 1u;
        } else {
            while (*((volatile unsigned*)&g_bar_sense) == sense) __nanosleep(32);
            __threadfence();
        }
    }
    sense ^= 1u;
    __syncthreads();
}

__device__ __forceinline__ void fma2(ull& a, ull x, ull w) {
    asm("fma.rn.f32x2 %0, %1, %2, %0;" : "+l"(a) : "l"(x), "l"(w));
}
__device__ __forceinline__ ull dup2(float w) {
    ull r; unsigned u = __float_as_uint(w);
    asm("mov.b64 %0, {%1,%1};" : "=l"(r) : "r"(u));
    return r;
}
__device__ __forceinline__ float2 u2f(ull v) {
    unsigned lo, hi;
    asm("mov.b64 {%0,%1}, %2;" : "=r"(lo), "=r"(hi) : "l"(v));
    float2 r; r.x = __uint_as_float(lo); r.y = __uint_as_float(hi);
    return r;
}
__device__ __forceinline__ float sigf(float x) { return 1.f / (1.f + __expf(-x)); }

// ---- 3-gate sub-GEMM, 64m x 16j x 3g CTA tile, thread = 4m x 1j x 3g ----
// sW4[k][j] = {w_gate0, w_gate1, w_gate2, pad}: inner loop = 2x LDS.128 + 3 dup + 6 FFMA2.
// Double-buffered smem, 1 __syncthreads per 32-k chunk.
template <int AMODE, int WMODE>
__device__ __forceinline__ void gemm3(
    const float* __restrict__ A, int ldA,
    const float* __restrict__ W, int ldW, int K,
    int m0, int j0, int tm, int tn,
    float* __restrict__ sA, float4* __restrict__ sW, ull (&acc)[2][3]) {
    const int tid = threadIdx.x;
    const int NC = K >> 5;
    float a_r[2][4];
    float w_r[2][3];

    auto ldg = [&](int kb) {
#pragma unroll
        for (int i = 0; i < 2; i++) {
            int f = tid + (i << 8);
            int k = f & 31, mg = f >> 5;      // mg 0..15
            int kk = kb + k;
#pragma unroll
            for (int r = 0; r < 4; r++) {
                int m = m0 + mg * 4 + r;
                if (AMODE == 1 && kk >= 128)
                    a_r[i][r] = g_embs[m * EMBD + (kk - 128)];
                else
                    a_r[i][r] = A[m * ldA + kk];
            }
        }
#pragma unroll
        for (int i = 0; i < 2; i++) {
            int f = tid + (i << 8);
            int k = f & 31, j = (f >> 5) & 15;
            int kk = kb + k;
            (void)WMODE;
#pragma unroll
            for (int g = 0; g < 3; g++)
                w_r[i][g] = W[((g << 9) + j0 + j) * ldW + kk];
        }
    };
    auto st = [&](int pb) {
        float* bA = sA + pb * (32 * 68);
        float4* bW = sW + pb * (32 * 17);
#pragma unroll
        for (int i = 0; i < 2; i++) {
            int f = tid + (i << 8);
            int k = f & 31, mg = f >> 5;
            *(float4*)&bA[k * 68 + mg * 4] =
                make_float4(a_r[i][0], a_r[i][1], a_r[i][2], a_r[i][3]);
        }
#pragma unroll
        for (int i = 0; i < 2; i++) {
            int f = tid + (i << 8);
            int k = f & 31, j = (f >> 5) & 15;
            bW[k * 17 + j] = make_float4(w_r[i][0], w_r[i][1], w_r[i][2], 0.f);
        }
    };
    auto comp = [&](int pb) {
        const float* bA = sA + pb * (32 * 68);
        const float4* bW = sW + pb * (32 * 17);
#pragma unroll 8
        for (int k = 0; k < 32; k++) {
            ulonglong2 av = *(const ulonglong2*)&bA[k * 68 + (tm << 2)];
            float4 w4 = bW[k * 17 + tn];
            ull w0 = dup2(w4.x), w1 = dup2(w4.y), w2 = dup2(w4.z);
            fma2(acc[0][0], av.x, w0); fma2(acc[1][0], av.y, w0);
            fma2(acc[0][1], av.x, w1); fma2(acc[1][1], av.y, w1);
            fma2(acc[0][2], av.x, w2); fma2(acc[1][2], av.y, w2);
        }
    };

    ldg(0);
    st(0);
    if (NC > 1) ldg(32);
    __syncthreads();
    for (int c = 0; c < NC; c++) {
        if (c + 1 < NC) {
            st((c + 1) & 1);
            if (c + 2 < NC) ldg((c + 2) << 5);
        }
        comp(c & 1);
        __syncthreads();
    }
}

template <bool PV>
__device__ __forceinline__ void combine3(
    ull (&aI)[2][3], ull (&aH)[2][3],
    const float* __restrict__ bias, const float* __restrict__ pvw,
    const float* __restrict__ hin, float* __restrict__ hout,
    int m0, int j0, int tm, int tn) {
    int j = j0 + tn;
    float bi0 = bias[tn], bi1 = bias[16 + tn], bi2 = bias[32 + tn];
    float bh0 = bias[48 + tn], bh1 = bias[64 + tn], bh2 = bias[80 + tn];
#pragma unroll
    for (int p = 0; p < 2; p++) {
        float2 vir = u2f(aI[p][0]), viz = u2f(aI[p][1]), vin = u2f(aI[p][2]);
        float2 vhr = u2f(aH[p][0]), vhz = u2f(aH[p][1]), vhn = u2f(aH[p][2]);
#pragma unroll
        for (int u = 0; u < 2; u++) {
            int b = m0 + (tm << 2) + (p << 1) + u;
            float ir = (u ? vir.y : vir.x) + bi0;
            float iz = (u ? viz.y : viz.x) + bi1;
            float in_ = (u ? vin.y : vin.x) + bi2;
            if (PV) {
                const float* pv = &g_pv[b * NPV];
#pragma unroll
                for (int q = 0; q < 5; q++) {
                    float pq = pv[q];
                    ir  += pq * pvw[tn * 5 + q];
                    iz  += pq * pvw[80 + tn * 5 + q];
                    in_ += pq * pvw[160 + tn * 5 + q];
                }
            }
            float hr = (u ? vhr.y : vhr.x) + bh0;
            float hz = (u ? vhz.y : vhz.x) + bh1;
            float hn = (u ? vhn.y : vhn.x) + bh2;
            float r = sigf(ir + hr);
            float z = sigf(iz + hz);
            float n = tanhf(in_ + r * hn);
            hout[b * H + j] = (1.f - z) * n + z * hin[b * H + j];
        }
    }
}

template <int AMODE, int WMODE, bool PV>
__device__ __forceinline__ void gru_step(
    const float* __restrict__ Ain, int ldA,
    const float* __restrict__ Wih, int ldWih, int Kin,
    const float* __restrict__ hin, const float* __restrict__ Whh,
    const float* __restrict__ bias, const float* __restrict__ pvw,
    float* __restrict__ hout,
    int m0, int j0, int tm, int tn, float* sA, float4* sW) {
    ull aI[2][3] = {{0, 0, 0}, {0, 0, 0}};
    ull aH[2][3] = {{0, 0, 0}, {0, 0, 0}};
    gemm3<AMODE, WMODE>(Ain, ldA, Wih, ldWih, Kin, m0, j0, tm, tn, sA, sW, aI);
    gemm3<0, 0>(hin, H, Whh, H, H, m0, j0, tm, tn, sA, sW, aH);
    combine3<PV>(aI, aH, bias, pvw, hin, hout, m0, j0, tm, tn);
}

// heads layer 1: z = relu(d2 @ [fc1|he1]^T + b), 256x256, K=512
__device__ __forceinline__ void heads1(const float* __restrict__ d2,
                                       const float* __restrict__ fc1W, const float* __restrict__ fc1b,
                                       const float* __restrict__ he1W, const float* __restrict__ he1b) {
    __shared__ float As2[32 * 17];
    __shared__ float Ws2[32 * 34];
    int tile = blockIdx.x;
    int m0 = (tile >> 3) * 16;
    int n0 = (tile & 7) * 32;
    int tid = threadIdx.x;
    int m = tid & 15;
    int n2 = (tid >> 4) * 2;

    float acc0 = 0.f, acc1 = 0.f;
    for (int kb = 0; kb < H; kb += 32) {
#pragma unroll
        for (int i = 0; i < 2; i++) {
            int lin = tid + i * NTHR;
            int kk = lin & 31, mm = lin >> 5;
            As2[kk * 17 + mm] = d2[(m0 + mm) * H + kb + kk];
        }
#pragma unroll
        for (int i = 0; i < 4; i++) {
            int lin = tid + i * NTHR;
            int kk = lin & 31, nn = lin >> 5;
            int ng = n0 + nn;
            const float* Wr = (ng < 128) ? (fc1W + ng * H) : (he1W + (ng - 128) * H);
            Ws2[kk * 34 + nn] = Wr[kb + kk];
        }
        __syncthreads();
#pragma unroll
        for (int k = 0; k < 32; k++) {
            float a = As2[k * 17 + m];
            float2 w = *(const float2*)&Ws2[k * 34 + n2];
            acc0 += a * w.x;
            acc1 += a * w.y;
        }
        __syncthreads();
    }
    int b = m0 + m;
    int ng0 = n0 + n2;
    float b0 = (ng0 < 128) ? fc1b[ng0] : he1b[ng0 - 128];
    float b1 = (ng0 + 1 < 128) ? fc1b[ng0 + 1] : he1b[ng0 + 1 - 128];
    g_z[b * 256 + ng0]     = fmaxf(acc0 + b0, 0.f);
    g_z[b * 256 + ng0 + 1] = fmaxf(acc1 + b1, 0.f);
}

__device__ __forceinline__ void heads2(int t,
                                       const float* __restrict__ fc2W, const float* __restrict__ fc2b,
                                       const float* __restrict__ he2W, const float* __restrict__ he2b,
                                       float* __restrict__ out) {
    __shared__ float zs[512];
    int tid = threadIdx.x;
    int b0 = blockIdx.x * 2;
    for (int i = tid; i < 512; i += NTHR) zs[i] = g_z[b0 * 256 + i];
    __syncthreads();
    int warp = tid >> 5, lane = tid & 31;
    for (int d = warp; d < 42; d += 8) {
        int bb = d / 21, o = d % 21;
        const float* wrow;
        int kbase;
        float bias;
        if (o < 5) { wrow = fc2W + o * 128; kbase = 0; bias = fc2b[o]; }
        else       { wrow = he2W + (o - 5) * 128; kbase = 128; bias = he2b[o - 5]; }
        float s = 0.f;
#pragma unroll
        for (int kk = 0; kk < 128; kk += 32)
            s += zs[bb * 256 + kbase + kk + lane] * wrow[kk + lane];
#pragma unroll
        for (int off = 16; off; off >>= 1) s += __shfl_xor_sync(0xffffffffu, s, off);
        if (lane == 0) {
            float v = s + bias;
            int b = b0 + bb;
            if (o < 5) {
                out[b * (TT * NPV) + t * NPV + o] = v;
                g_pv[b * NPV + o] = v;
            } else {
                out[B * TT * NPV + b * (TT * NHE) + t * NHE + (o - 5)] = v;
            }
        }
    }
    __syncthreads();
}

struct P {
    const float *x_cv, *x_cv_target, *pv_init;
    const int* scenario;
    const float* emb;
    const float *eW0i, *eW0h, *eb0i, *eb0h, *eW1i, *eW1h, *eb1i, *eb1h;
    const float *dW0i, *dW0h, *db0i, *db0h, *dW1i, *dW1h, *db1i, *db1h;
    const float *fc1W, *fc1b, *fc2W, *fc2b, *he1W, *he1b, *he2W, *he2b;
    float* out;
};

__global__ void __launch_bounds__(NTHR, 1) gru_kernel(P p) {
    __shared__ __align__(16) float sA[2 * 32 * 68];
    __shared__ __align__(16) float4 sW[2 * 32 * 17];
    __shared__ float sBias[4 * 96];
    __shared__ float sPvw[240];

    unsigned sense = *((volatile unsigned*)&g_bar_sense);
    int tid = threadIdx.x;
    int mt = blockIdx.x >> 5, jt = blockIdx.x & 31;
    int m0 = mt << 6, j0 = jt << 4;
    int tm = tid >> 4, tn = tid & 15;
    int gt = blockIdx.x * NTHR + tid;

    for (int i = gt; i < B * H; i += NBLK * NTHR) { g_h0a[i] = 0.f; g_h1a[i] = 0.f; }
    for (int i = gt; i < B * EMBD; i += NBLK * NTHR)
        g_embs[i] = p.emb[p.scenario[i >> 5] * EMBD + (i & 31)];
    for (int i = gt; i < B * NPV; i += NBLK * NTHR) g_pv[i] = p.pv_init[i];

    {
        const float* bI[4] = { p.eb0i, p.eb1i, p.db0i, p.db1i };
        const float* bH[4] = { p.eb0h, p.eb1h, p.db0h, p.db1h };
        for (int idx = tid; idx < 384; idx += NTHR) {
            int ph = idx / 96, r = idx % 96, g = r >> 4, jj = r & 15;
            sBias[idx] = (g < 3) ? bI[ph][(g << 9) + j0 + jj]
                                 : bH[ph][((g - 3) << 9) + j0 + jj];
        }
        for (int idx = tid; idx < 240; idx += NTHR) {
            int g = idx / 80, r = idx % 80, jj = r / 5, q = r % 5;
            sPvw[idx] = p.dW0i[((g << 9) + j0 + jj) * 133 + 128 + q];
        }
    }
    gsync(sense);

    float* h0buf[2] = { g_h0a, g_h0b };
    float* h1buf[2] = { g_h1a, g_h1b };

    // encoder: 1 grid barrier per step (ping-pong + program order make the rest safe)
    for (int t = 0; t < TE; t++) {
        int rd = t & 1, wr = rd ^ 1;
        gru_step<1, 0, false>(p.x_cv + t * NIN, TE * NIN, p.eW0i, 160, 160,
                              h0buf[rd], p.eW0h, sBias, nullptr,
                              h0buf[wr], m0, j0, tm, tn, sA, sW);
        gsync(sense);
        gru_step<0, 0, false>(h0buf[wr], H, p.eW1i, 512, 512,
                              h1buf[rd], p.eW1h, sBias + 96, nullptr,
                              h1buf[wr], m0, j0, tm, tn, sA, sW);
    }

    // decoder
    for (int t = 0; t < TT; t++) {
        int rd = t & 1, wr = rd ^ 1;
        gru_step<0, 1, true>(p.x_cv_target + t * NIN, TT * NIN, p.dW0i, 133, 128,
                             h0buf[rd], p.dW0h, sBias + 192, sPvw,
                             h0buf[wr], m0, j0, tm, tn, sA, sW);
        gsync(sense);
        gru_step<0, 0, false>(h0buf[wr], H, p.dW1i, 512, 512,
                              h1buf[rd], p.dW1h, sBias + 288, nullptr,
                              h1buf[wr], m0, j0, tm, tn, sA, sW);
        gsync(sense);
        heads1(h1buf[wr], p.fc1W, p.fc1b, p.he1W, p.he1b);
        gsync(sense);
        heads2(t, p.fc2W, p.fc2b, p.he2W, p.he2b, p.out);
        gsync(sense);
    }
}

extern "C" void kernel_launch(void* const* d_in, const int* in_sizes, int n_in,
                              void* d_out, int out_size) {
    (void)in_sizes; (void)n_in; (void)out_size;
    P p;
    p.x_cv        = (const float*)d_in[0];
    p.x_cv_target = (const float*)d_in[1];
    p.pv_init     = (const float*)d_in[2];
    p.scenario    = (const int*)d_in[3];
    p.emb         = (const float*)d_in[4];
    p.eW0i = (const float*)d_in[5];  p.eW0h = (const float*)d_in[6];
    p.eb0i = (const float*)d_in[7];  p.eb0h = (const float*)d_in[8];
    p.eW1i = (const float*)d_in[9];  p.eW1h = (const float*)d_in[10];
    p.eb1i = (const float*)d_in[11]; p.eb1h = (const float*)d_in[12];
    p.dW0i = (const float*)d_in[13]; p.dW0h = (const float*)d_in[14];
    p.db0i = (const float*)d_in[15]; p.db0h = (const float*)d_in[16];
    p.dW1i = (const float*)d_in[17]; p.dW1h = (const float*)d_in[18];
    p.db1i = (const float*)d_in[19]; p.db1h = (const float*)d_in[20];
    p.fc1W = (const float*)d_in[21]; p.fc1b = (const float*)d_in[22];
    p.fc2W = (const float*)d_in[23]; p.fc2b = (const float*)d_in[24];
    p.he1W = (const float*)d_in[25]; p.he1b = (const float*)d_in[26];
    p.he2W = (const float*)d_in[27]; p.he2b = (const float*)d_in[28];
    p.out  = (float*)d_out;
    gru_kernel<<<NBLK, NTHR>>>(p);
}

// round 6
// speedup vs baseline: 1.0151x; 1.0151x over previous
#include <cuda_runtime.h>

#define NBLK 128
#define NTHR 256
#define B 256
#define TE 300
#define TT 600
#define H 512
#define NIN 128
#define NPV 5
#define EMBD 32
#define NHE 16

typedef unsigned long long ull;

__device__ float g_h0a[B * H], g_h0b[B * H];
__device__ float g_h1a[B * H], g_h1b[B * H];
__device__ float g_z[B * 256];
__device__ float g_pv[B * NPV];
__device__ float g_embs[B * EMBD];
__device__ unsigned g_bar_count;
__device__ unsigned g_bar_sense;

__device__ __forceinline__ void gsync(unsigned& sense) {
    __syncthreads();
    if (threadIdx.x == 0) {
        __threadfence();
        unsigned prev = atomicAdd(&g_bar_count, 1u);
        if (prev == (unsigned)(NBLK - 1)) {
            atomicExch(&g_bar_count, 0u);
            __threadfence();
            *((volatile unsigned*)&g_bar_sense) = sense ^ 1u;
        } else {
            while (*((volatile unsigned*)&g_bar_sense) == sense) __nanosleep(32);
            __threadfence();
        }
    }
    sense ^= 1u;
    __syncthreads();
}

__device__ __forceinline__ void fma2(ull& a, ull x, ull w) {
    asm("fma.rn.f32x2 %0, %1, %2, %0;" : "+l"(a) : "l"(x), "l"(w));
}
__device__ __forceinline__ ull dup2(float w) {
    ull r; unsigned u = __float_as_uint(w);
    asm("mov.b64 %0, {%1,%1};" : "=l"(r) : "r"(u));
    return r;
}
__device__ __forceinline__ float2 u2f(ull v) {
    unsigned lo, hi;
    asm("mov.b64 {%0,%1}, %2;" : "=r"(lo), "=r"(hi) : "l"(v));
    float2 r; r.x = __uint_as_float(lo); r.y = __uint_as_float(hi);
    return r;
}
__device__ __forceinline__ float sigf(float x) { return 1.f / (1.f + __expf(-x)); }

// ---- 3-gate sub-GEMM, 64m x 16j x 3g CTA tile, thread = 4m x 1j x 3g ----
// sW4[k][j] = {w_gate0, w_gate1, w_gate2, pad}: inner loop = 2x LDS.128 + 3 dup + 6 FFMA2.
// Double-buffered smem, 1 __syncthreads per 32-k chunk.
template <int AMODE, int WMODE>
__device__ __forceinline__ void gemm3(
    const float* __restrict__ A, int ldA,
    const float* __restrict__ W, int ldW, int K,
    int m0, int j0, int tm, int tn,
    float* __restrict__ sA, float4* __restrict__ sW, ull (&acc)[2][3]) {
    const int tid = threadIdx.x;
    const int NC = K >> 5;
    float a_r[2][4];
    float w_r[2][3];

    auto ldg = [&](int kb) {
#pragma unroll
        for (int i = 0; i < 2; i++) {
            int f = tid + (i << 8);
            int k = f & 31, mg = f >> 5;      // mg 0..15
            int kk = kb + k;
#pragma unroll
            for (int r = 0; r < 4; r++) {
                int m = m0 + mg * 4 + r;
                if (AMODE == 1 && kk >= 128)
                    a_r[i][r] = g_embs[m * EMBD + (kk - 128)];
                else
                    a_r[i][r] = A[m * ldA + kk];
            }
        }
#pragma unroll
        for (int i = 0; i < 2; i++) {
            int f = tid + (i << 8);
            int k = f & 31, j = (f >> 5) & 15;
            int kk = kb + k;
            (void)WMODE;
#pragma unroll
            for (int g = 0; g < 3; g++)
                w_r[i][g] = W[((g << 9) + j0 + j) * ldW + kk];
        }
    };
    auto st = [&](int pb) {
        float* bA = sA + pb * (32 * 68);
        float4* bW = sW + pb * (32 * 17);
#pragma unroll
        for (int i = 0; i < 2; i++) {
            int f = tid + (i << 8);
            int k = f & 31, mg = f >> 5;
            *(float4*)&bA[k * 68 + mg * 4] =
                make_float4(a_r[i][0], a_r[i][1], a_r[i][2], a_r[i][3]);
        }
#pragma unroll
        for (int i = 0; i < 2; i++) {
            int f = tid + (i << 8);
            int k = f & 31, j = (f >> 5) & 15;
            bW[k * 17 + j] = make_float4(w_r[i][0], w_r[i][1], w_r[i][2], 0.f);
        }
    };
    auto comp = [&](int pb) {
        const float* bA = sA + pb * (32 * 68);
        const float4* bW = sW + pb * (32 * 17);
#pragma unroll 8
        for (int k = 0; k < 32; k++) {
            ulonglong2 av = *(const ulonglong2*)&bA[k * 68 + (tm << 2)];
            float4 w4 = bW[k * 17 + tn];
            ull w0 = dup2(w4.x), w1 = dup2(w4.y), w2 = dup2(w4.z);
            fma2(acc[0][0], av.x, w0); fma2(acc[1][0], av.y, w0);
            fma2(acc[0][1], av.x, w1); fma2(acc[1][1], av.y, w1);
            fma2(acc[0][2], av.x, w2); fma2(acc[1][2], av.y, w2);
        }
    };

    ldg(0);
    st(0);
    if (NC > 1) ldg(32);
    __syncthreads();
    for (int c = 0; c < NC; c++) {
        if (c + 1 < NC) {
            st((c + 1) & 1);
            if (c + 2 < NC) ldg((c + 2) << 5);
        }
        comp(c & 1);
        __syncthreads();
    }
}

template <bool PV>
__device__ __forceinline__ void combine3(
    ull (&aI)[2][3], ull (&aH)[2][3],
    const float* __restrict__ bias, const float* __restrict__ pvw,
    const float* __restrict__ hin, float* __restrict__ hout,
    int m0, int j0, int tm, int tn) {
    int j = j0 + tn;
    float bi0 = bias[tn], bi1 = bias[16 + tn], bi2 = bias[32 + tn];
    float bh0 = bias[48 + tn], bh1 = bias[64 + tn], bh2 = bias[80 + tn];
#pragma unroll
    for (int p = 0; p < 2; p++) {
        float2 vir = u2f(aI[p][0]), viz = u2f(aI[p][1]), vin = u2f(aI[p][2]);
        float2 vhr = u2f(aH[p][0]), vhz = u2f(aH[p][1]), vhn = u2f(aH[p][2]);
#pragma unroll
        for (int u = 0; u < 2; u++) {
            int b = m0 + (tm << 2) + (p << 1) + u;
            float ir = (u ? vir.y : vir.x) + bi0;
            float iz = (u ? viz.y : viz.x) + bi1;
            float in_ = (u ? vin.y : vin.x) + bi2;
            if (PV) {
                const float* pv = &g_pv[b * NPV];
#pragma unroll
                for (int q = 0; q < 5; q++) {
                    float pq = pv[q];
                    ir  += pq * pvw[tn * 5 + q];
                    iz  += pq * pvw[80 + tn * 5 + q];
                    in_ += pq * pvw[160 + tn * 5 + q];
                }
            }
            float hr = (u ? vhr.y : vhr.x) + bh0;
            float hz = (u ? vhz.y : vhz.x) + bh1;
            float hn = (u ? vhn.y : vhn.x) + bh2;
            float r = sigf(ir + hr);
            float z = sigf(iz + hz);
            float n = tanhf(in_ + r * hn);
            hout[b * H + j] = (1.f - z) * n + z * hin[b * H + j];
        }
    }
}

template <int AMODE, int WMODE, bool PV>
__device__ __forceinline__ void gru_step(
    const float* __restrict__ Ain, int ldA,
    const float* __restrict__ Wih, int ldWih, int Kin,
    const float* __restrict__ hin, const float* __restrict__ Whh,
    const float* __restrict__ bias, const float* __restrict__ pvw,
    float* __restrict__ hout,
    int m0, int j0, int tm, int tn, float* sA, float4* sW) {
    ull aI[2][3] = {{0, 0, 0}, {0, 0, 0}};
    ull aH[2][3] = {{0, 0, 0}, {0, 0, 0}};
    gemm3<AMODE, WMODE>(Ain, ldA, Wih, ldWih, Kin, m0, j0, tm, tn, sA, sW, aI);
    gemm3<0, 0>(hin, H, Whh, H, H, m0, j0, tm, tn, sA, sW, aH);
    combine3<PV>(aI, aH, bias, pvw, hin, hout, m0, j0, tm, tn);
}

// heads layer 1: z = relu(d2 @ [fc1|he1]^T + b), 256x256, K=512
__device__ __forceinline__ void heads1(const float* __restrict__ d2,
                                       const float* __restrict__ fc1W, const float* __restrict__ fc1b,
                                       const float* __restrict__ he1W, const float* __restrict__ he1b) {
    __shared__ float As2[32 * 17];
    __shared__ float Ws2[32 * 34];
    int tile = blockIdx.x;
    int m0 = (tile >> 3) * 16;
    int n0 = (tile & 7) * 32;
    int tid = threadIdx.x;
    int m = tid & 15;
    int n2 = (tid >> 4) * 2;

    float acc0 = 0.f, acc1 = 0.f;
    for (int kb = 0; kb < H; kb += 32) {
#pragma unroll
        for (int i = 0; i < 2; i++) {
            int lin = tid + i * NTHR;
            int kk = lin & 31, mm = lin >> 5;
            As2[kk * 17 + mm] = d2[(m0 + mm) * H + kb + kk];
        }
#pragma unroll
        for (int i = 0; i < 4; i++) {
            int lin = tid + i * NTHR;
            int kk = lin & 31, nn = lin >> 5;
            int ng = n0 + nn;
            const float* Wr = (ng < 128) ? (fc1W + ng * H) : (he1W + (ng - 128) * H);
            Ws2[kk * 34 + nn] = Wr[kb + kk];
        }
        __syncthreads();
#pragma unroll
        for (int k = 0; k < 32; k++) {
            float a = As2[k * 17 + m];
            float2 w = *(const float2*)&Ws2[k * 34 + n2];
            acc0 += a * w.x;
            acc1 += a * w.y;
        }
        __syncthreads();
    }
    int b = m0 + m;
    int ng0 = n0 + n2;
    float b0 = (ng0 < 128) ? fc1b[ng0] : he1b[ng0 - 128];
    float b1 = (ng0 + 1 < 128) ? fc1b[ng0 + 1] : he1b[ng0 + 1 - 128];
    g_z[b * 256 + ng0]     = fmaxf(acc0 + b0, 0.f);
    g_z[b * 256 + ng0 + 1] = fmaxf(acc1 + b1, 0.f);
}

__device__ __forceinline__ void heads2(int t,
                                       const float* __restrict__ fc2W, const float* __restrict__ fc2b,
                                       const float* __restrict__ he2W, const float* __restrict__ he2b,
                                       float* __restrict__ out) {
    __shared__ float zs[512];
    int tid = threadIdx.x;
    int b0 = blockIdx.x * 2;
    for (int i = tid; i < 512; i += NTHR) zs[i] = g_z[b0 * 256 + i];
    __syncthreads();
    int warp = tid >> 5, lane = tid & 31;
    for (int d = warp; d < 42; d += 8) {
        int bb = d / 21, o = d % 21;
        const float* wrow;
        int kbase;
        float bias;
        if (o < 5) { wrow = fc2W + o * 128; kbase = 0; bias = fc2b[o]; }
        else       { wrow = he2W + (o - 5) * 128; kbase = 128; bias = he2b[o - 5]; }
        float s = 0.f;
#pragma unroll
        for (int kk = 0; kk < 128; kk += 32)
            s += zs[bb * 256 + kbase + kk + lane] * wrow[kk + lane];
#pragma unroll
        for (int off = 16; off; off >>= 1) s += __shfl_xor_sync(0xffffffffu, s, off);
        if (lane == 0) {
            float v = s + bias;
            int b = b0 + bb;
            if (o < 5) {
                out[b * (TT * NPV) + t * NPV + o] = v;
                g_pv[b * NPV + o] = v;
            } else {
                out[B * TT * NPV + b * (TT * NHE) + t * NHE + (o - 5)] = v;
            }
        }
    }
    __syncthreads();
}

struct P {
    const float *x_cv, *x_cv_target, *pv_init;
    const int* scenario;
    const float* emb;
    const float *eW0i, *eW0h, *eb0i, *eb0h, *eW1i, *eW1h, *eb1i, *eb1h;
    const float *dW0i, *dW0h, *db0i, *db0h, *dW1i, *dW1h, *db1i, *db1h;
    const float *fc1W, *fc1b, *fc2W, *fc2b, *he1W, *he1b, *he2W, *he2b;
    float* out;
};

__global__ void __launch_bounds__(NTHR, 1) gru_kernel(P p) {
    __shared__ __align__(16) float sA[2 * 32 * 68];
    __shared__ __align__(16) float4 sW[2 * 32 * 17];
    __shared__ float sBias[4 * 96];
    __shared__ float sPvw[240];

    unsigned sense = *((volatile unsigned*)&g_bar_sense);
    int tid = threadIdx.x;
    int mt = blockIdx.x >> 5, jt = blockIdx.x & 31;
    int m0 = mt << 6, j0 = jt << 4;
    int tm = tid >> 4, tn = tid & 15;
    int gt = blockIdx.x * NTHR + tid;

    for (int i = gt; i < B * H; i += NBLK * NTHR) { g_h0a[i] = 0.f; g_h1a[i] = 0.f; }
    for (int i = gt; i < B * EMBD; i += NBLK * NTHR)
        g_embs[i] = p.emb[p.scenario[i >> 5] * EMBD + (i & 31)];
    for (int i = gt; i < B * NPV; i += NBLK * NTHR) g_pv[i] = p.pv_init[i];

    {
        const float* bI[4] = { p.eb0i, p.eb1i, p.db0i, p.db1i };
        const float* bH[4] = { p.eb0h, p.eb1h, p.db0h, p.db1h };
        for (int idx = tid; idx < 384; idx += NTHR) {
            int ph = idx / 96, r = idx % 96, g = r >> 4, jj = r & 15;
            sBias[idx] = (g < 3) ? bI[ph][(g << 9) + j0 + jj]
                                 : bH[ph][((g - 3) << 9) + j0 + jj];
        }
        for (int idx = tid; idx < 240; idx += NTHR) {
            int g = idx / 80, r = idx % 80, jj = r / 5, q = r % 5;
            sPvw[idx] = p.dW0i[((g << 9) + j0 + jj) * 133 + 128 + q];
        }
    }
    gsync(sense);

    float* h0buf[2] = { g_h0a, g_h0b };
    float* h1buf[2] = { g_h1a, g_h1b };

    // encoder: 1 grid barrier per step (ping-pong + program order make the rest safe)
    for (int t = 0; t < TE; t++) {
        int rd = t & 1, wr = rd ^ 1;
        gru_step<1, 0, false>(p.x_cv + t * NIN, TE * NIN, p.eW0i, 160, 160,
                              h0buf[rd], p.eW0h, sBias, nullptr,
                              h0buf[wr], m0, j0, tm, tn, sA, sW);
        gsync(sense);
        gru_step<0, 0, false>(h0buf[wr], H, p.eW1i, 512, 512,
                              h1buf[rd], p.eW1h, sBias + 96, nullptr,
                              h1buf[wr], m0, j0, tm, tn, sA, sW);
    }

    // decoder
    for (int t = 0; t < TT; t++) {
        int rd = t & 1, wr = rd ^ 1;
        gru_step<0, 1, true>(p.x_cv_target + t * NIN, TT * NIN, p.dW0i, 133, 128,
                             h0buf[rd], p.dW0h, sBias + 192, sPvw,
                             h0buf[wr], m0, j0, tm, tn, sA, sW);
        gsync(sense);
        gru_step<0, 0, false>(h0buf[wr], H, p.dW1i, 512, 512,
                              h1buf[rd], p.dW1h, sBias + 288, nullptr,
                              h1buf[wr], m0, j0, tm, tn, sA, sW);
        gsync(sense);
        heads1(h1buf[wr], p.fc1W, p.fc1b, p.he1W, p.he1b);
        gsync(sense);
        heads2(t, p.fc2W, p.fc2b, p.he2W, p.he2b, p.out);
        gsync(sense);
    }
}

extern "C" void kernel_launch(void* const* d_in, const int* in_sizes, int n_in,
                              void* d_out, int out_size) {
    (void)in_sizes; (void)n_in; (void)out_size;
    P p;
    p.x_cv        = (const float*)d_in[0];
    p.x_cv_target = (const float*)d_in[1];
    p.pv_init     = (const float*)d_in[2];
    p.scenario    = (const int*)d_in[3];
    p.emb         = (const float*)d_in[4];
    p.eW0i = (const float*)d_in[5];  p.eW0h = (const float*)d_in[6];
    p.eb0i = (const float*)d_in[7];  p.eb0h = (const float*)d_in[8];
    p.eW1i = (const float*)d_in[9];  p.eW1h = (const float*)d_in[10];
    p.eb1i = (const float*)d_in[11]; p.eb1h = (const float*)d_in[12];
    p.dW0i = (const float*)d_in[13]; p.dW0h = (const float*)d_in[14];
    p.db0i = (const float*)d_in[15]; p.db0h = (const float*)d_in[16];
    p.dW1i = (const float*)d_in[17]; p.dW1h = (const float*)d_in[18];
    p.db1i = (const float*)d_in[19]; p.db1h = (const float*)d_in[20];
    p.fc1W = (const float*)d_in[21]; p.fc1b = (const float*)d_in[22];
    p.fc2W = (const float*)d_in[23]; p.fc2b = (const float*)d_in[24];
    p.he1W = (const float*)d_in[25]; p.he1b = (const float*)d_in[26];
    p.he2W = (const float*)d_in[27]; p.he2b = (const float*)d_in[28];
    p.out  = (float*)d_out;
    gru_kernel<<<NBLK, NTHR>>>(p);
}

// round 7
// speedup vs baseline: 1.4346x; 1.4132x over previous
#include <cuda_runtime.h>
#include <cuda_bf16.h>

#define NBLK 128
#define NTHR 256
#define B 256
#define TE 300
#define TT 600
#define H 512
#define NIN 128
#define NPV 5
#define EMBD 32
#define NHE 16

__device__ float g_h0a[B * H], g_h0b[B * H];
__device__ float g_h1a[B * H], g_h1b[B * H];
__device__ float g_z[B * 256];
__device__ float g_pv[B * NPV];
__device__ float g_embs[B * EMBD];
__device__ unsigned g_bar_count;
__device__ unsigned g_bar_sense;

__device__ __forceinline__ void gsync(unsigned& sense) {
    __syncthreads();
    if (threadIdx.x == 0) {
        __threadfence();
        unsigned prev = atomicAdd(&g_bar_count, 1u);
        if (prev == (unsigned)(NBLK - 1)) {
            atomicExch(&g_bar_count, 0u);
            __threadfence();
            *((volatile unsigned*)&g_bar_sense) = sense ^ 1u;
        } else {
            while (*((volatile unsigned*)&g_bar_sense) == sense) __nanosleep(32);
            __threadfence();
        }
    }
    sense ^= 1u;
    __syncthreads();
}

__device__ __forceinline__ float sigf(float x) { return 1.f / (1.f + __expf(-x)); }

__device__ __forceinline__ void ldm4(unsigned* r, unsigned a) {
    asm volatile("ldmatrix.sync.aligned.m8n8.x4.shared.b16 {%0,%1,%2,%3},[%4];"
        : "=r"(r[0]), "=r"(r[1]), "=r"(r[2]), "=r"(r[3]) : "r"(a));
}
__device__ __forceinline__ void ldm2(unsigned* r, unsigned a) {
    asm volatile("ldmatrix.sync.aligned.m8n8.x2.shared.b16 {%0,%1},[%2];"
        : "=r"(r[0]), "=r"(r[1]) : "r"(a));
}
__device__ __forceinline__ void mmabf(float* d, const unsigned* a, const unsigned* b) {
    asm volatile("mma.sync.aligned.m16n8k16.row.col.f32.bf16.bf16.f32 "
        "{%0,%1,%2,%3},{%4,%5,%6,%7},{%8,%9},{%0,%1,%2,%3};"
        : "+f"(d[0]), "+f"(d[1]), "+f"(d[2]), "+f"(d[3])
        : "r"(a[0]), "r"(a[1]), "r"(a[2]), "r"(a[3]), "r"(b[0]), "r"(b[1]));
}
__device__ __forceinline__ void cvtpack(float4 v, unsigned& h01, unsigned& h23,
                                        unsigned& l01, unsigned& l23) {
    __nv_bfloat16 h0 = __float2bfloat16(v.x), h1 = __float2bfloat16(v.y);
    __nv_bfloat16 h2 = __float2bfloat16(v.z), h3 = __float2bfloat16(v.w);
    __nv_bfloat16 l0 = __float2bfloat16(v.x - __bfloat162float(h0));
    __nv_bfloat16 l1 = __float2bfloat16(v.y - __bfloat162float(h1));
    __nv_bfloat16 l2 = __float2bfloat16(v.z - __bfloat162float(h2));
    __nv_bfloat16 l3 = __float2bfloat16(v.w - __bfloat162float(h3));
    h01 = ((unsigned)__bfloat16_as_ushort(h1) << 16) | __bfloat16_as_ushort(h0);
    h23 = ((unsigned)__bfloat16_as_ushort(h3) << 16) | __bfloat16_as_ushort(h2);
    l01 = ((unsigned)__bfloat16_as_ushort(l1) << 16) | __bfloat16_as_ushort(l0);
    l23 = ((unsigned)__bfloat16_as_ushort(l3) << 16) | __bfloat16_as_ushort(l2);
}

// ---- 3-gate GEMM via bf16 hi/lo 3-pass mma.sync. CTA 64m x 48n (n = g*16+j).
// Result (no bias) -> sG[64][52] fp32. AMODE1: concat x(128)+emb. WMODE1: scalar W loads (ld 133).
template <int AMODE, int WMODE>
__device__ void gemm3(const float* __restrict__ A, int ldA,
                      const float* __restrict__ W, int ldW, int K,
                      int m0, int j0,
                      __nv_bfloat16* sAh, __nv_bfloat16* sAl,
                      __nv_bfloat16* sWh, __nv_bfloat16* sWl,
                      float* __restrict__ sG) {
    const int tid = threadIdx.x, lane = tid & 31, warp = tid >> 5;
    const int wm = warp >> 1, wn = warp & 1;
    const int NC = K >> 5;
    float4 ar[2], wr[2];
    float d[3][4] = {{0, 0, 0, 0}, {0, 0, 0, 0}, {0, 0, 0, 0}};

    auto ldg = [&](int kb) {
#pragma unroll
        for (int i = 0; i < 2; i++) {
            int f = tid + (i << 8), m = f >> 3, kq = f & 7, kk = kb + (kq << 2);
            if (AMODE == 1 && kk >= 128)
                ar[i] = *(const float4*)&g_embs[(m0 + m) * EMBD + (kk - 128)];
            else
                ar[i] = *(const float4*)&A[(m0 + m) * ldA + kk];
        }
#pragma unroll
        for (int i = 0; i < 2; i++) {
            int f = tid + (i << 8);
            if (f < 384) {
                int n = f >> 3, kq = f & 7, kk = kb + (kq << 2);
                int grow = ((n >> 4) << 9) + j0 + (n & 15);
                if (WMODE == 0) wr[i] = *(const float4*)&W[grow * ldW + kk];
                else {
                    const float* p = &W[grow * ldW + kk];
                    wr[i] = make_float4(p[0], p[1], p[2], p[3]);
                }
            }
        }
    };
    auto st = [&](int pb) {
        __nv_bfloat16 *ah = sAh + pb * 2560, *al = sAl + pb * 2560;
        __nv_bfloat16 *wh = sWh + pb * 1920, *wl = sWl + pb * 1920;
#pragma unroll
        for (int i = 0; i < 2; i++) {
            int f = tid + (i << 8), m = f >> 3, kq = f & 7, o = m * 40 + (kq << 2);
            unsigned a0, a1, b0, b1;
            cvtpack(ar[i], a0, a1, b0, b1);
            *(uint2*)&ah[o] = make_uint2(a0, a1);
            *(uint2*)&al[o] = make_uint2(b0, b1);
        }
#pragma unroll
        for (int i = 0; i < 2; i++) {
            int f = tid + (i << 8);
            if (f < 384) {
                int n = f >> 3, kq = f & 7, o = n * 40 + (kq << 2);
                unsigned a0, a1, b0, b1;
                cvtpack(wr[i], a0, a1, b0, b1);
                *(uint2*)&wh[o] = make_uint2(a0, a1);
                *(uint2*)&wl[o] = make_uint2(b0, b1);
            }
        }
    };
    // per-lane ldmatrix row offsets (elements)
    const int arow = wm * 16 + (((lane >> 3) & 1) << 3) + (lane & 7);
    const int akoff = (lane >> 4) << 3;
    const int l8 = lane & 15;
    const int brow = l8 & 7, bk = ((l8 >> 3) & 1) << 3;

    auto comp = [&](int pb) {
        const __nv_bfloat16 *ah = sAh + pb * 2560, *al = sAl + pb * 2560;
        const __nv_bfloat16 *wh = sWh + pb * 1920, *wl = sWl + pb * 1920;
        unsigned Ah[2][4], Al[2][4], Wh[2][3][2], Wl[2][3][2];
#pragma unroll
        for (int ks = 0; ks < 2; ks++) {
            ldm4(Ah[ks], (unsigned)__cvta_generic_to_shared(&ah[arow * 40 + (ks << 4) + akoff]));
            ldm4(Al[ks], (unsigned)__cvta_generic_to_shared(&al[arow * 40 + (ks << 4) + akoff]));
        }
#pragma unroll
        for (int nb = 0; nb < 3; nb++) {
            int nrow = wn * 24 + nb * 8 + brow;
#pragma unroll
            for (int ks = 0; ks < 2; ks++) {
                ldm2(Wh[ks][nb], (unsigned)__cvta_generic_to_shared(&wh[nrow * 40 + (ks << 4) + bk]));
                ldm2(Wl[ks][nb], (unsigned)__cvta_generic_to_shared(&wl[nrow * 40 + (ks << 4) + bk]));
            }
        }
#pragma unroll
        for (int ks = 0; ks < 2; ks++)
#pragma unroll
            for (int nb = 0; nb < 3; nb++) {
                mmabf(d[nb], Ah[ks], Wh[ks][nb]);
                mmabf(d[nb], Ah[ks], Wl[ks][nb]);
                mmabf(d[nb], Al[ks], Wh[ks][nb]);
            }
    };

    ldg(0); st(0);
    if (NC > 1) ldg(32);
    __syncthreads();
    for (int c = 0; c < NC; c++) {
        if (c + 1 < NC) { st((c + 1) & 1); if (c + 2 < NC) ldg((c + 2) << 5); }
        comp(c & 1);
        __syncthreads();
    }
    int mrow = wm * 16 + (lane >> 2);
#pragma unroll
    for (int nb = 0; nb < 3; nb++) {
        int n = wn * 24 + nb * 8 + ((lane & 3) << 1);
        *(float2*)&sG[mrow * 52 + n] = make_float2(d[nb][0], d[nb][1]);
        *(float2*)&sG[(mrow + 8) * 52 + n] = make_float2(d[nb][2], d[nb][3]);
    }
}

template <bool PV>
__device__ __forceinline__ void combine3(const float* sGi, const float* sGh,
                                         const float* bias, const float* pvw,
                                         const float* __restrict__ hin, float* __restrict__ hout,
                                         int m0, int j0, int tm, int tn) {
    int j = j0 + tn;
    float bi0 = bias[tn], bi1 = bias[16 + tn], bi2 = bias[32 + tn];
    float bh0 = bias[48 + tn], bh1 = bias[64 + tn], bh2 = bias[80 + tn];
#pragma unroll
    for (int r = 0; r < 4; r++) {
        int ml = (tm << 2) + r, b = m0 + ml;
        float ir = sGi[ml * 52 + tn] + bi0;
        float iz = sGi[ml * 52 + 16 + tn] + bi1;
        float in_ = sGi[ml * 52 + 32 + tn] + bi2;
        if (PV) {
            const float* pv = &g_pv[b * NPV];
#pragma unroll
            for (int q = 0; q < 5; q++) {
                float pq = pv[q];
                ir += pq * pvw[tn * 5 + q];
                iz += pq * pvw[80 + tn * 5 + q];
                in_ += pq * pvw[160 + tn * 5 + q];
            }
        }
        float hr = sGh[ml * 52 + tn] + bh0;
        float hz = sGh[ml * 52 + 16 + tn] + bh1;
        float hn = sGh[ml * 52 + 32 + tn] + bh2;
        float rr = sigf(ir + hr), zz = sigf(iz + hz), nn = tanhf(in_ + rr * hn);
        hout[b * H + j] = (1.f - zz) * nn + zz * hin[b * H + j];
    }
}

__device__ void heads1(float* As2, float* Ws2, const float* __restrict__ d2,
                       const float* __restrict__ fc1W, const float* __restrict__ fc1b,
                       const float* __restrict__ he1W, const float* __restrict__ he1b) {
    int tile = blockIdx.x;
    int m0 = (tile >> 3) * 16, n0 = (tile & 7) * 32;
    int tid = threadIdx.x, m = tid & 15, n2 = (tid >> 4) * 2;
    float acc0 = 0.f, acc1 = 0.f;
    for (int kb = 0; kb < H; kb += 32) {
#pragma unroll
        for (int i = 0; i < 2; i++) {
            int lin = tid + i * NTHR, kk = lin & 31, mm = lin >> 5;
            As2[kk * 17 + mm] = d2[(m0 + mm) * H + kb + kk];
        }
#pragma unroll
        for (int i = 0; i < 4; i++) {
            int lin = tid + i * NTHR, kk = lin & 31, nn = lin >> 5;
            int ng = n0 + nn;
            const float* Wr = (ng < 128) ? (fc1W + ng * H) : (he1W + (ng - 128) * H);
            Ws2[kk * 34 + nn] = Wr[kb + kk];
        }
        __syncthreads();
#pragma unroll
        for (int k = 0; k < 32; k++) {
            float a = As2[k * 17 + m];
            float2 w = *(const float2*)&Ws2[k * 34 + n2];
            acc0 += a * w.x; acc1 += a * w.y;
        }
        __syncthreads();
    }
    int b = m0 + m, ng0 = n0 + n2;
    float b0 = (ng0 < 128) ? fc1b[ng0] : he1b[ng0 - 128];
    float b1 = (ng0 + 1 < 128) ? fc1b[ng0 + 1] : he1b[ng0 + 1 - 128];
    g_z[b * 256 + ng0] = fmaxf(acc0 + b0, 0.f);
    g_z[b * 256 + ng0 + 1] = fmaxf(acc1 + b1, 0.f);
}

__device__ void heads2(float* zs, int t,
                       const float* __restrict__ fc2W, const float* __restrict__ fc2b,
                       const float* __restrict__ he2W, const float* __restrict__ he2b,
                       float* __restrict__ out) {
    int tid = threadIdx.x, b0 = blockIdx.x * 2;
    for (int i = tid; i < 512; i += NTHR) zs[i] = g_z[b0 * 256 + i];
    __syncthreads();
    int warp = tid >> 5, lane = tid & 31;
    for (int dd = warp; dd < 42; dd += 8) {
        int bb = dd / 21, o = dd % 21;
        const float* wrow; int kbase; float bias;
        if (o < 5) { wrow = fc2W + o * 128; kbase = 0; bias = fc2b[o]; }
        else       { wrow = he2W + (o - 5) * 128; kbase = 128; bias = he2b[o - 5]; }
        float s = 0.f;
#pragma unroll
        for (int kk = 0; kk < 128; kk += 32)
            s += zs[bb * 256 + kbase + kk + lane] * wrow[kk + lane];
#pragma unroll
        for (int off = 16; off; off >>= 1) s += __shfl_xor_sync(0xffffffffu, s, off);
        if (lane == 0) {
            float v = s + bias; int b = b0 + bb;
            if (o < 5) { out[b * (TT * NPV) + t * NPV + o] = v; g_pv[b * NPV + o] = v; }
            else out[B * TT * NPV + b * (TT * NHE) + t * NHE + (o - 5)] = v;
        }
    }
    __syncthreads();
}

struct P {
    const float *x_cv, *x_cv_target, *pv_init;
    const int* scenario;
    const float* emb;
    const float *eW0i, *eW0h, *eb0i, *eb0h, *eW1i, *eW1h, *eb1i, *eb1h;
    const float *dW0i, *dW0h, *db0i, *db0h, *dW1i, *dW1h, *db1i, *db1h;
    const float *fc1W, *fc1b, *fc2W, *fc2b, *he1W, *he1b, *he2W, *he2b;
    float* out;
};

#define SMEM_BYTES 73536

__global__ void __launch_bounds__(NTHR, 1) gru_kernel(P p) {
    extern __shared__ __align__(16) char sm[];
    __nv_bfloat16* sAh = (__nv_bfloat16*)sm;            // 2*2560
    __nv_bfloat16* sAl = sAh + 5120;                    // 2*2560
    __nv_bfloat16* sWh = sAl + 5120;                    // 2*1920
    __nv_bfloat16* sWl = sWh + 3840;                    // 2*1920
    float* sGi = (float*)(sWl + 3840);                  // 64*52
    float* sGh = sGi + 64 * 52;
    float* sBias = sGh + 64 * 52;                       // 384
    float* sPvw = sBias + 384;                          // 240
    float* sH = sPvw + 240;                             // heads: 544 + 1088 + 512

    unsigned sense = *((volatile unsigned*)&g_bar_sense);
    int tid = threadIdx.x;
    int mt = blockIdx.x >> 5, jt = blockIdx.x & 31;
    int m0 = mt << 6, j0 = jt << 4;
    int tm = tid >> 4, tn = tid & 15;
    int gt = blockIdx.x * NTHR + tid;

    for (int i = gt; i < B * H; i += NBLK * NTHR) { g_h0a[i] = 0.f; g_h1a[i] = 0.f; }
    for (int i = gt; i < B * EMBD; i += NBLK * NTHR)
        g_embs[i] = p.emb[p.scenario[i >> 5] * EMBD + (i & 31)];
    for (int i = gt; i < B * NPV; i += NBLK * NTHR) g_pv[i] = p.pv_init[i];
    {
        const float* bI[4] = { p.eb0i, p.eb1i, p.db0i, p.db1i };
        const float* bH[4] = { p.eb0h, p.eb1h, p.db0h, p.db1h };
        for (int idx = tid; idx < 384; idx += NTHR) {
            int ph = idx / 96, r = idx % 96, g = r >> 4, jj = r & 15;
            sBias[idx] = (g < 3) ? bI[ph][(g << 9) + j0 + jj] : bH[ph][((g - 3) << 9) + j0 + jj];
        }
        for (int idx = tid; idx < 240; idx += NTHR) {
            int g = idx / 80, r = idx % 80, jj = r / 5, q = r % 5;
            sPvw[idx] = p.dW0i[((g << 9) + j0 + jj) * 133 + 128 + q];
        }
    }
    gsync(sense);

    float* h0buf[2] = { g_h0a, g_h0b };
    float* h1buf[2] = { g_h1a, g_h1b };

    for (int t = 0; t < TE; t++) {
        int rd = t & 1, wr = rd ^ 1;
        gemm3<1, 0>(p.x_cv + t * NIN, TE * NIN, p.eW0i, 160, 160, m0, j0, sAh, sAl, sWh, sWl, sGi);
        gemm3<0, 0>(h0buf[rd], H, p.eW0h, H, H, m0, j0, sAh, sAl, sWh, sWl, sGh);
        __syncthreads();
        combine3<false>(sGi, sGh, sBias, nullptr, h0buf[rd], h0buf[wr], m0, j0, tm, tn);
        gsync(sense);
        gemm3<0, 0>(h0buf[wr], H, p.eW1i, H, H, m0, j0, sAh, sAl, sWh, sWl, sGi);
        gemm3<0, 0>(h1buf[rd], H, p.eW1h, H, H, m0, j0, sAh, sAl, sWh, sWl, sGh);
        __syncthreads();
        combine3<false>(sGi, sGh, sBias + 96, nullptr, h1buf[rd], h1buf[wr], m0, j0, tm, tn);
    }

    for (int t = 0; t < TT; t++) {
        int rd = t & 1, wr = rd ^ 1;
        gemm3<0, 1>(p.x_cv_target + t * NIN, TT * NIN, p.dW0i, 133, 128, m0, j0, sAh, sAl, sWh, sWl, sGi);
        gemm3<0, 0>(h0buf[rd], H, p.dW0h, H, H, m0, j0, sAh, sAl, sWh, sWl, sGh);
        __syncthreads();
        combine3<true>(sGi, sGh, sBias + 192, sPvw, h0buf[rd], h0buf[wr], m0, j0, tm, tn);
        gsync(sense);
        gemm3<0, 0>(h0buf[wr], H, p.dW1i, H, H, m0, j0, sAh, sAl, sWh, sWl, sGi);
        gemm3<0, 0>(h1buf[rd], H, p.dW1h, H, H, m0, j0, sAh, sAl, sWh, sWl, sGh);
        __syncthreads();
        combine3<false>(sGi, sGh, sBias + 288, nullptr, h1buf[rd], h1buf[wr], m0, j0, tm, tn);
        gsync(sense);
        heads1(sH, sH + 544, h1buf[wr], p.fc1W, p.fc1b, p.he1W, p.he1b);
        gsync(sense);
        heads2(sH + 544 + 1088, t, p.fc2W, p.fc2b, p.he2W, p.he2b, p.out);
        gsync(sense);
    }
}

extern "C" void kernel_launch(void* const* d_in, const int* in_sizes, int n_in,
                              void* d_out, int out_size) {
    (void)in_sizes; (void)n_in; (void)out_size;
    cudaFuncSetAttribute(gru_kernel, cudaFuncAttributeMaxDynamicSharedMemorySize, SMEM_BYTES);
    P p;
    p.x_cv        = (const float*)d_in[0];
    p.x_cv_target = (const float*)d_in[1];
    p.pv_init     = (const float*)d_in[2];
    p.scenario    = (const int*)d_in[3];
    p.emb         = (const float*)d_in[4];
    p.eW0i = (const float*)d_in[5];  p.eW0h = (const float*)d_in[6];
    p.eb0i = (const float*)d_in[7];  p.eb0h = (const float*)d_in[8];
    p.eW1i = (const float*)d_in[9];  p.eW1h = (const float*)d_in[10];
    p.eb1i = (const float*)d_in[11]; p.eb1h = (const float*)d_in[12];
    p.dW0i = (const float*)d_in[13]; p.dW0h = (const float*)d_in[14];
    p.db0i = (const float*)d_in[15]; p.db0h = (const float*)d_in[16];
    p.dW1i = (const float*)d_in[17]; p.dW1h = (const float*)d_in[18];
    p.db1i = (const float*)d_in[19]; p.db1h = (const float*)d_in[20];
    p.fc1W = (const float*)d_in[21]; p.fc1b = (const float*)d_in[22];
    p.fc2W = (const float*)d_in[23]; p.fc2b = (const float*)d_in[24];
    p.he1W = (const float*)d_in[25]; p.he1b = (const float*)d_in[26];
    p.he2W = (const float*)d_in[27]; p.he2b = (const float*)d_in[28];
    p.out  = (float*)d_out;
    gru_kernel<<<NBLK, NTHR, SMEM_BYTES>>>(p);
}